// round 1
// baseline (speedup 1.0000x reference)
#include <cuda_runtime.h>

// QLinear: y[m,n] = sum_k x[m,k] * ((q[n,k]-8)*s[g,n] + z[g,n]) + bias[n]
// M=32, K=4096, N=11008, group=32. Weight stored one int32 per int4 value.
// Dequant folded: w = q*s + (z - 8s).

#define MM 32
#define KK 4096
#define NN 11008
#define KC 128          // K-chunk staged in smem (4 quant groups)
#define NT 4            // output columns per warp
#define NWARPS 4
#define BN (NT*NWARPS)  // 16 columns per block
#define THREADS (NWARPS*32)

__global__ __launch_bounds__(THREADS)
void qlinear_kernel(const float* __restrict__ x,
                    const int*   __restrict__ w,
                    const float* __restrict__ sz,
                    const float* __restrict__ bias,
                    float* __restrict__ out)
{
    // xs row stride 132 floats: keeps lane-major LDS.128 conflict-free and 16B-aligned
    __shared__ float xs[MM][KC + 4];
    __shared__ float wq[NWARPS][NT][KC];
    __shared__ float res[MM][BN + 1];

    const int tid    = threadIdx.x;
    const int lane   = tid & 31;
    const int wid    = tid >> 5;
    const int nblock = blockIdx.x * BN;
    const int nbase  = nblock + wid * NT;

    // weight-dequant lane mapping: 8 lanes per output column
    const int nl  = lane >> 3;            // 0..3 : column within warp
    const int n_w = nbase + nl;           // global output column this lane dequants
    const int kb  = (lane & 7) << 2;      // 0..28 : offset within a 32-wide group

    float acc0 = 0.f, acc1 = 0.f, acc2 = 0.f, acc3 = 0.f;

    for (int k0 = 0; k0 < KK; k0 += KC) {
        // ---- stage x chunk: xs[m][kk], coalesced 512B per warp per row ----
        #pragma unroll
        for (int i = 0; i < (MM * (KC/4)) / THREADS; i++) {
            int idx = tid + i * THREADS;
            int m   = idx >> 5;        // KC/4 == 32
            int kk4 = idx & 31;
            float4 v = *(const float4*)(x + (size_t)m * KK + k0 + kk4 * 4);
            *(float4*)(&xs[m][kk4 * 4]) = v;
        }

        // ---- dequant this warp's NT weight columns into smem ----
        {
            const int* wrow = w + (size_t)n_w * KK + k0;
            #pragma unroll
            for (int j = 0; j < 4; j++) {           // 4 groups per 128-chunk
                int g = (k0 >> 5) + j;
                float2 s2 = *(const float2*)(sz + ((size_t)g * NN + n_w) * 2);
                float s = s2.x;
                float c = s2.y - 8.0f * s;          // zero - 8*scale
                int4 q = *(const int4*)(wrow + j * 32 + kb);
                float4 f;
                f.x = (float)q.x * s + c;
                f.y = (float)q.y * s + c;
                f.z = (float)q.z * s + c;
                f.w = (float)q.w * s + c;
                *(float4*)(&wq[wid][nl][j * 32 + kb]) = f;
            }
        }
        __syncthreads();

        // ---- compute: lane = m, 4 output columns per warp ----
        #pragma unroll
        for (int kk = 0; kk < KC; kk += 4) {
            float4 xv = *(const float4*)(&xs[lane][kk]);
            float4 w0 = *(const float4*)(&wq[wid][0][kk]);  // uniform -> broadcast
            float4 w1 = *(const float4*)(&wq[wid][1][kk]);
            float4 w2 = *(const float4*)(&wq[wid][2][kk]);
            float4 w3 = *(const float4*)(&wq[wid][3][kk]);
            acc0 += xv.x * w0.x; acc0 += xv.y * w0.y; acc0 += xv.z * w0.z; acc0 += xv.w * w0.w;
            acc1 += xv.x * w1.x; acc1 += xv.y * w1.y; acc1 += xv.z * w1.z; acc1 += xv.w * w1.w;
            acc2 += xv.x * w2.x; acc2 += xv.y * w2.y; acc2 += xv.z * w2.z; acc2 += xv.w * w2.w;
            acc3 += xv.x * w3.x; acc3 += xv.y * w3.y; acc3 += xv.z * w3.z; acc3 += xv.w * w3.w;
        }
        __syncthreads();
    }

    // ---- stage results and write coalesced ----
    res[lane][wid * NT + 0] = acc0;
    res[lane][wid * NT + 1] = acc1;
    res[lane][wid * NT + 2] = acc2;
    res[lane][wid * NT + 3] = acc3;
    __syncthreads();

    #pragma unroll
    for (int i = 0; i < (MM * BN) / THREADS; i++) {
        int idx = tid + i * THREADS;
        int m   = idx / BN;
        int nl2 = idx % BN;
        int n   = nblock + nl2;
        out[(size_t)m * NN + n] = res[m][nl2] + bias[n];
    }
}

extern "C" void kernel_launch(void* const* d_in, const int* in_sizes, int n_in,
                              void* d_out, int out_size) {
    const float* x    = (const float*)d_in[0];
    const int*   w    = (const int*)d_in[1];
    const float* sz   = (const float*)d_in[2];
    const float* bias = (const float*)d_in[3];
    float* out = (float*)d_out;
    qlinear_kernel<<<NN / BN, THREADS>>>(x, w, sz, bias, out);
}

// round 3
// speedup vs baseline: 1.0953x; 1.0953x over previous
#include <cuda_runtime.h>

// QLinear int4-group dequant GEMM. M=32, K=4096, N=11008, group=32.
// y[m,n] = sum_k x[m,k]*((q-8)*s + z) + bias
// Exact dequant bit trick:
//   f = as_float(q | 0x4B000000) = 2^23 + q
//   t = f - (2^23 + 8)            (exact: Sterbenz, t = q - 8)
//   w = fma(t, s, z)              (single rounding)

#define MM 32
#define KK 4096
#define NN 11008
#define KC 128
#define BN 16
#define THREADS 128
#define WQ_S 20          // wq row stride in floats (bank-engineered, 16B-aligned)

__device__ float g_xT[KK * MM];   // x transposed: [k][m]

__global__ void transpose_x(const float* __restrict__ x) {
    int g = blockIdx.x * blockDim.x + threadIdx.x;   // g = k*32 + m
    if (g < KK * MM) {
        int k = g >> 5, m = g & 31;
        g_xT[g] = x[(size_t)m * KK + k];
    }
}

__device__ __forceinline__ unsigned long long ffma2(unsigned long long a,
                                                    unsigned long long b,
                                                    unsigned long long c) {
    unsigned long long d;
    asm("fma.rn.f32x2 %0, %1, %2, %3;" : "=l"(d) : "l"(a), "l"(b), "l"(c));
    return d;
}

__device__ __forceinline__ unsigned long long splat2(float w) {
    unsigned long long p;
    asm("mov.b64 %0, {%1, %1};" : "=l"(p) : "f"(w));
    return p;
}

__device__ __forceinline__ float dq1(int q, float s, float z) {
    float f = __int_as_float(q | 0x4B000000);   // 2^23 + q
    float t = f - 8388616.0f;                   // exact: q - 8
    return __fmaf_rn(t, s, z);
}

__global__ __launch_bounds__(THREADS)
void qlinear2(const int* __restrict__ w, const float* __restrict__ sz,
              const float* __restrict__ bias, float* __restrict__ out)
{
    __shared__ float xs[KC * MM];          // [k][m], flat copy of xT chunk
    __shared__ float wq[KC][WQ_S];         // dequantized weights [k][n]
    __shared__ float res[4][MM][BN + 4];   // per-warp partials

    const int tid  = threadIdx.x;
    const int lane = tid & 31;
    const int wid  = tid >> 5;
    const int nb   = blockIdx.x * BN;

    // compute mapping: 8 m-groups x 4 n-groups per warp
    const int mg = lane & 7;        const int m0 = mg * 4;
    const int ng = lane >> 3;       const int n0 = ng * 4;

    // dequant mapping: n = tid&15, kk4 varies
    const int dq_n = tid & 15;

    unsigned long long acc[2][4];
    #pragma unroll
    for (int p = 0; p < 2; p++)
        #pragma unroll
        for (int j = 0; j < 4; j++) acc[p][j] = 0ull;

    for (int k0 = 0; k0 < KK; k0 += KC) {
        // ---- stage x chunk: straight float4 copy of g_xT[k0*32 ..] ----
        const float4* xsrc = (const float4*)(g_xT + (size_t)k0 * MM);
        float4* xdst = (float4*)xs;
        #pragma unroll
        for (int i = 0; i < (KC * MM / 4) / THREADS; i++)   // 8 iters
            xdst[i * THREADS + tid] = xsrc[i * THREADS + tid];

        // ---- dequant weights: BN*KC = 2048 values ----
        #pragma unroll
        for (int i = 0; i < 4; i++) {
            int idx = i * THREADS + tid;          // 0..511 int4-units
            int kk4 = idx >> 4;                    // 0..31
            int kk  = kk4 * 4;
            int g   = (k0 >> 5) + (kk4 >> 3);
            float2 s2 = ((const float2*)sz)[(size_t)g * NN + nb + dq_n];
            float s = s2.x;
            float z = s2.y;
            int4 q = *(const int4*)(w + (size_t)(nb + dq_n) * KK + k0 + kk);
            wq[kk + 0][dq_n] = dq1(q.x, s, z);
            wq[kk + 1][dq_n] = dq1(q.y, s, z);
            wq[kk + 2][dq_n] = dq1(q.z, s, z);
            wq[kk + 3][dq_n] = dq1(q.w, s, z);
        }
        __syncthreads();

        // ---- compute: this warp handles kk = wid*32 .. +31 ----
        const int kbeg = wid * 32;
        #pragma unroll 4
        for (int kk = kbeg; kk < kbeg + 32; kk++) {
            // x pairs (m0,m0+1),(m0+2,m0+3) loaded as one 16B LDS
            double2 xp = *(const double2*)(xs + kk * MM + m0);
            unsigned long long xp0 = __double_as_longlong(xp.x);
            unsigned long long xp1 = __double_as_longlong(xp.y);
            float4 wv = *(const float4*)(&wq[kk][n0]);
            unsigned long long w0 = splat2(wv.x);
            unsigned long long w1 = splat2(wv.y);
            unsigned long long w2 = splat2(wv.z);
            unsigned long long w3 = splat2(wv.w);
            acc[0][0] = ffma2(xp0, w0, acc[0][0]);
            acc[0][1] = ffma2(xp0, w1, acc[0][1]);
            acc[0][2] = ffma2(xp0, w2, acc[0][2]);
            acc[0][3] = ffma2(xp0, w3, acc[0][3]);
            acc[1][0] = ffma2(xp1, w0, acc[1][0]);
            acc[1][1] = ffma2(xp1, w1, acc[1][1]);
            acc[1][2] = ffma2(xp1, w2, acc[1][2]);
            acc[1][3] = ffma2(xp1, w3, acc[1][3]);
        }
        __syncthreads();
    }

    // ---- write per-warp partials ----
    {
        #pragma unroll
        for (int p = 0; p < 2; p++) {
            float4 lo, hi;  // lo: m0+2p row, values for n0..n0+3
            lo.x = __uint_as_float((unsigned)(acc[p][0] & 0xFFFFFFFFull));
            lo.y = __uint_as_float((unsigned)(acc[p][1] & 0xFFFFFFFFull));
            lo.z = __uint_as_float((unsigned)(acc[p][2] & 0xFFFFFFFFull));
            lo.w = __uint_as_float((unsigned)(acc[p][3] & 0xFFFFFFFFull));
            hi.x = __uint_as_float((unsigned)(acc[p][0] >> 32));
            hi.y = __uint_as_float((unsigned)(acc[p][1] >> 32));
            hi.z = __uint_as_float((unsigned)(acc[p][2] >> 32));
            hi.w = __uint_as_float((unsigned)(acc[p][3] >> 32));
            *(float4*)(&res[wid][m0 + 2 * p + 0][n0]) = lo;
            *(float4*)(&res[wid][m0 + 2 * p + 1][n0]) = hi;
        }
    }
    __syncthreads();

    // ---- cross-warp reduce + bias + store ----
    {
        int m  = tid >> 2;          // 0..31
        int nq = tid & 3;           // 0..3 -> n chunk of 4
        float4 a0 = *(const float4*)(&res[0][m][nq * 4]);
        float4 a1 = *(const float4*)(&res[1][m][nq * 4]);
        float4 a2 = *(const float4*)(&res[2][m][nq * 4]);
        float4 a3 = *(const float4*)(&res[3][m][nq * 4]);
        float4 b  = *(const float4*)(bias + nb + nq * 4);
        float4 o;
        o.x = a0.x + a1.x + a2.x + a3.x + b.x;
        o.y = a0.y + a1.y + a2.y + a3.y + b.y;
        o.z = a0.z + a1.z + a2.z + a3.z + b.z;
        o.w = a0.w + a1.w + a2.w + a3.w + b.w;
        *(float4*)(out + (size_t)m * NN + nb + nq * 4) = o;
    }
}

extern "C" void kernel_launch(void* const* d_in, const int* in_sizes, int n_in,
                              void* d_out, int out_size) {
    const float* x    = (const float*)d_in[0];
    const int*   wgt  = (const int*)d_in[1];
    const float* sz   = (const float*)d_in[2];
    const float* bias = (const float*)d_in[3];
    float* out = (float*)d_out;
    transpose_x<<<(KK * MM + 255) / 256, 256>>>(x);
    qlinear2<<<NN / BN, THREADS>>>(wgt, sz, bias, out);
}

// round 4
// speedup vs baseline: 1.3886x; 1.2677x over previous
#include <cuda_runtime.h>

// QLinear int4-group dequant GEMM. M=32, K=4096, N=11008, group=32.
// MT=8 x NT=8 register tile per lane, fma.rn.f32x2, k-split over 8 partials.

#define MM 32
#define KK 4096
#define NN 11008
#define KC 64
#define BN 64
#define KSPAN 1024      // K per block (4 k-quarters)
#define THREADS 64

typedef unsigned long long ull;

__device__ float g_xT[KK * MM];           // x transposed [k][m]
__device__ float g_part[8 * MM * NN];     // 8 k-partials

__global__ void transpose_x(const float* __restrict__ x) {
    int g = blockIdx.x * blockDim.x + threadIdx.x;
    if (g < KK * MM) {
        int k = g >> 5, m = g & 31;
        g_xT[g] = x[(size_t)m * KK + k];
    }
}

__device__ __forceinline__ ull ffma2(ull a, ull b, ull c) {
    ull d;
    asm("fma.rn.f32x2 %0, %1, %2, %3;" : "=l"(d) : "l"(a), "l"(b), "l"(c));
    return d;
}
__device__ __forceinline__ ull splat2(float w) {
    ull p;
    asm("mov.b64 %0, {%1, %1};" : "=l"(p) : "f"(w));
    return p;
}
__device__ __forceinline__ float dq1(int q, float s, float z) {
    float f = __int_as_float(q | 0x4B000000);   // 2^23 + q
    float t = f - 8388616.0f;                   // exact: q - 8
    return __fmaf_rn(t, s, z);
}
__device__ __forceinline__ float lo2(ull a) { return __uint_as_float((unsigned)a); }
__device__ __forceinline__ float hi2(ull a) { return __uint_as_float((unsigned)(a >> 32)); }

__global__ __launch_bounds__(THREADS)
void qlinear3(const int* __restrict__ w, const float* __restrict__ sz)
{
    __shared__ __align__(16) float xs[KC * MM];    // [kk][m]  8KB
    __shared__ __align__(16) float wq[KC][BN];     // [kk][n] 16KB

    const int tid  = threadIdx.x;
    const int lane = tid & 31;
    const int wid  = tid >> 5;
    const int nt   = blockIdx.x >> 2;
    const int kq   = blockIdx.x & 3;
    const int nb   = nt * BN;
    const int kbeg = kq * KSPAN;

    const int mg = lane & 3;   const int m0 = mg * 8;
    const int ng = lane >> 2;  const int n0 = ng * 8;

    ull acc[4][8];
    #pragma unroll
    for (int mi = 0; mi < 4; mi++)
        #pragma unroll
        for (int nj = 0; nj < 8; nj++) acc[mi][nj] = 0ull;

    const int* wrow = w + (size_t)(nb + tid) * KK + kbeg;   // this thread's n column
    const float2* szp = (const float2*)sz;

    for (int c = 0; c < KSPAN / KC; c++) {
        const int k0 = kbeg + c * KC;

        // ---- stage x chunk (straight float4 copy from transposed x) ----
        const float4* xsrc = (const float4*)(g_xT + (size_t)k0 * MM);
        #pragma unroll
        for (int i = 0; i < (KC * MM / 4) / THREADS; i++)    // 8 iters
            ((float4*)xs)[i * THREADS + tid] = xsrc[i * THREADS + tid];

        // ---- dequant: thread owns column n = nb+tid, kk = 0..63 ----
        {
            const int g0 = k0 >> 5;
            float2 s0 = szp[(size_t)g0 * NN + nb + tid];
            float2 s1 = szp[(size_t)(g0 + 1) * NN + nb + tid];
            #pragma unroll
            for (int j = 0; j < 16; j++) {
                int4 q = *(const int4*)(wrow + c * KC + j * 4);
                float s = (j < 8) ? s0.x : s1.x;
                float z = (j < 8) ? s0.y : s1.y;
                wq[j * 4 + 0][tid] = dq1(q.x, s, z);
                wq[j * 4 + 1][tid] = dq1(q.y, s, z);
                wq[j * 4 + 2][tid] = dq1(q.z, s, z);
                wq[j * 4 + 3][tid] = dq1(q.w, s, z);
            }
        }
        __syncthreads();

        // ---- compute: warp wid handles kk = wid*32 .. +31 ----
        const int kk0 = wid * 32;
        #pragma unroll 4
        for (int kk = kk0; kk < kk0 + 32; kk++) {
            ull xp[4];
            {
                double2 da = *(const double2*)(xs + kk * MM + m0);
                double2 db = *(const double2*)(xs + kk * MM + m0 + 4);
                xp[0] = __double_as_longlong(da.x);
                xp[1] = __double_as_longlong(da.y);
                xp[2] = __double_as_longlong(db.x);
                xp[3] = __double_as_longlong(db.y);
            }
            float wv[8];
            *(float4*)(wv)     = *(const float4*)(&wq[kk][n0]);
            *(float4*)(wv + 4) = *(const float4*)(&wq[kk][n0 + 4]);
            ull ws[8];
            #pragma unroll
            for (int nj = 0; nj < 8; nj++) ws[nj] = splat2(wv[nj]);
            #pragma unroll
            for (int mi = 0; mi < 4; mi++)
                #pragma unroll
                for (int nj = 0; nj < 8; nj++)
                    acc[mi][nj] = ffma2(xp[mi], ws[nj], acc[mi][nj]);
        }
        __syncthreads();
    }

    // ---- write this (block,warp)'s k-partial: slot p = kq*2 + wid ----
    float* pbase = g_part + (size_t)(kq * 2 + wid) * (MM * NN);
    #pragma unroll
    for (int mi = 0; mi < 4; mi++) {
        int me = m0 + 2 * mi;
        float4 e0 = make_float4(lo2(acc[mi][0]), lo2(acc[mi][1]), lo2(acc[mi][2]), lo2(acc[mi][3]));
        float4 e1 = make_float4(lo2(acc[mi][4]), lo2(acc[mi][5]), lo2(acc[mi][6]), lo2(acc[mi][7]));
        float4 o0 = make_float4(hi2(acc[mi][0]), hi2(acc[mi][1]), hi2(acc[mi][2]), hi2(acc[mi][3]));
        float4 o1 = make_float4(hi2(acc[mi][4]), hi2(acc[mi][5]), hi2(acc[mi][6]), hi2(acc[mi][7]));
        *(float4*)(pbase + (size_t)me * NN + nb + n0)           = e0;
        *(float4*)(pbase + (size_t)me * NN + nb + n0 + 4)       = e1;
        *(float4*)(pbase + (size_t)(me + 1) * NN + nb + n0)     = o0;
        *(float4*)(pbase + (size_t)(me + 1) * NN + nb + n0 + 4) = o1;
    }
}

__global__ void reduce_out(const float* __restrict__ bias, float* __restrict__ out)
{
    int i = blockIdx.x * blockDim.x + threadIdx.x;     // float4 index
    const int TOT4 = MM * NN / 4;                       // 88064
    if (i < TOT4) {
        float4 a = make_float4(0.f, 0.f, 0.f, 0.f);
        #pragma unroll
        for (int p = 0; p < 8; p++) {
            float4 v = ((const float4*)g_part)[(size_t)p * TOT4 + i];
            a.x += v.x; a.y += v.y; a.z += v.z; a.w += v.w;
        }
        int n4 = i % (NN / 4);
        float4 b = ((const float4*)bias)[n4];
        a.x += b.x; a.y += b.y; a.z += b.z; a.w += b.w;
        ((float4*)out)[i] = a;
    }
}

extern "C" void kernel_launch(void* const* d_in, const int* in_sizes, int n_in,
                              void* d_out, int out_size) {
    const float* x    = (const float*)d_in[0];
    const int*   wgt  = (const int*)d_in[1];
    const float* sz   = (const float*)d_in[2];
    const float* bias = (const float*)d_in[3];
    float* out = (float*)d_out;
    transpose_x<<<(KK * MM + 255) / 256, 256>>>(x);
    qlinear3<<<(NN / BN) * 4, THREADS>>>(wgt, sz);
    reduce_out<<<(MM * NN / 4 + 127) / 128, 128>>>(bias, out);
}